// round 1
// baseline (speedup 1.0000x reference)
#include <cuda_runtime.h>

// Problem constants: x [2, 64, 64, 96, 96]; NSEQ = bs*c = 128; T = d = 64; HID = 4
#define NSEQ 128
#define TSTEPS 64
#define ROWELEMS 9216      // 96*96
#define ROWVEC 2304        // 9216/4
#define ELEMS_PER_BC 589824  // 64*96*96
#define VECS_PER_BC 147456   // ELEMS_PER_BC/4

__device__ float g_mean[NSEQ * TSTEPS];   // [seq=b*64+c][t=d]
__device__ float g_last[NSEQ * 8];        // last-timestep [fwd h(4) | bwd h(4)]
__device__ float g_scale[NSEQ];           // sigmoid output per (b,c)

__device__ __forceinline__ float sigf(float x) {
    return __fdividef(1.f, 1.f + __expf(-x));
}
__device__ __forceinline__ float tanhfast(float x) {
    return __fdividef(2.f, 1.f + __expf(-2.f * x)) - 1.f;
}

// ---------------------------------------------------------------------------
// Kernel 1: mean over H,W for each (b,c,d) row. One block per row.
// ---------------------------------------------------------------------------
__global__ void mean_kernel(const float* __restrict__ x) {
    int r = blockIdx.x;  // 0..8191
    const float4* p = reinterpret_cast<const float4*>(x) + (size_t)r * ROWVEC;
    float s = 0.f;
#pragma unroll
    for (int i = 0; i < 9; ++i) {
        float4 v = p[threadIdx.x + i * 256];
        s += (v.x + v.y) + (v.z + v.w);
    }
#pragma unroll
    for (int off = 16; off > 0; off >>= 1)
        s += __shfl_down_sync(0xffffffffu, s, off);
    __shared__ float red[8];
    int warp = threadIdx.x >> 5, lane = threadIdx.x & 31;
    if (lane == 0) red[warp] = s;
    __syncthreads();
    if (threadIdx.x < 8) {
        s = red[threadIdx.x];
        s += __shfl_down_sync(0xffu, s, 4);
        s += __shfl_down_sync(0xffu, s, 2);
        s += __shfl_down_sync(0xffu, s, 1);
        if (threadIdx.x == 0) g_mean[r] = s * (1.f / 9216.f);
    }
}

// ---------------------------------------------------------------------------
// Kernel 2: 2-layer biLSTM (hidden=4). 8 blocks x 32 threads.
// Block handles 16 sequences. Thread = (seq_local = tid>>1, dir = tid&1).
// Layer-0 outputs staged in SMEM. Layer-1: fwd runs all 64 steps (threads
// 0..15); bwd only needs its FIRST step, since only t=63 of the final output
// sequence is consumed (threads 16..31).
// ---------------------------------------------------------------------------
__global__ void lstm_kernel(
    const float* __restrict__ wih0f, const float* __restrict__ whh0f,
    const float* __restrict__ bih0f, const float* __restrict__ bhh0f,
    const float* __restrict__ wih0b, const float* __restrict__ whh0b,
    const float* __restrict__ bih0b, const float* __restrict__ bhh0b,
    const float* __restrict__ wih1f, const float* __restrict__ whh1f,
    const float* __restrict__ bih1f, const float* __restrict__ bhh1f,
    const float* __restrict__ wih1b, const float* __restrict__ whh1b,
    const float* __restrict__ bih1b, const float* __restrict__ bhh1b) {
    // per-seq row stride 516 floats (64*8 + 4 pad) to soften bank conflicts
    __shared__ float s_h0[16 * 516];
    __shared__ float s_wih0[2][16], s_whh0[2][64], s_b0[2][16];
    __shared__ float s_wih1[2][128], s_whh1[2][64], s_b1[2][16];

    int tid = threadIdx.x;
    {
        const float* WIH0[2] = {wih0f, wih0b};
        const float* WHH0[2] = {whh0f, whh0b};
        const float* BI0[2]  = {bih0f, bih0b};
        const float* BH0[2]  = {bhh0f, bhh0b};
        const float* WIH1[2] = {wih1f, wih1b};
        const float* WHH1[2] = {whh1f, whh1b};
        const float* BI1[2]  = {bih1f, bih1b};
        const float* BH1[2]  = {bhh1f, bhh1b};
        for (int d = 0; d < 2; ++d) {
            for (int k = tid; k < 16; k += 32) {
                s_wih0[d][k] = WIH0[d][k];
                s_b0[d][k] = BI0[d][k] + BH0[d][k];
                s_b1[d][k] = BI1[d][k] + BH1[d][k];
            }
            for (int k = tid; k < 64; k += 32) {
                s_whh0[d][k] = WHH0[d][k];
                s_whh1[d][k] = WHH1[d][k];
            }
            for (int k = tid; k < 128; k += 32) s_wih1[d][k] = WIH1[d][k];
        }
    }
    __syncthreads();

    // ---------------- layer 0 ----------------
    {
        int seq_local = tid >> 1;
        int dir = tid & 1;
        int seq = blockIdx.x * 16 + seq_local;
        float h[4] = {0, 0, 0, 0}, c[4] = {0, 0, 0, 0};
        const float* mrow = g_mean + seq * TSTEPS;
        float* hrow = s_h0 + seq_local * 516;
        for (int s = 0; s < TSTEPS; ++s) {
            int t = dir ? (TSTEPS - 1 - s) : s;
            float xt = mrow[t];
            float gate[16];
#pragma unroll
            for (int k = 0; k < 16; ++k) {
                float a = fmaf(s_wih0[dir][k], xt, s_b0[dir][k]);
#pragma unroll
                for (int j = 0; j < 4; ++j) a = fmaf(s_whh0[dir][k * 4 + j], h[j], a);
                gate[k] = a;
            }
#pragma unroll
            for (int j = 0; j < 4; ++j) {
                float ig = sigf(gate[j]), fg = sigf(gate[4 + j]);
                float gg = tanhfast(gate[8 + j]), og = sigf(gate[12 + j]);
                c[j] = fmaf(fg, c[j], ig * gg);
                h[j] = og * tanhfast(c[j]);
                hrow[t * 8 + dir * 4 + j] = h[j];
            }
        }
    }
    __syncthreads();

    // ---------------- layer 1 ----------------
    if (tid < 16) {
        // forward: full 64 steps, keep final h
        int sq = blockIdx.x * 16 + tid;
        const float* hrow = s_h0 + tid * 516;
        float h[4] = {0, 0, 0, 0}, c[4] = {0, 0, 0, 0};
        for (int t = 0; t < TSTEPS; ++t) {
            float xt[8];
#pragma unroll
            for (int m = 0; m < 8; ++m) xt[m] = hrow[t * 8 + m];
            float gate[16];
#pragma unroll
            for (int k = 0; k < 16; ++k) {
                float a = s_b1[0][k];
#pragma unroll
                for (int m = 0; m < 8; ++m) a = fmaf(s_wih1[0][k * 8 + m], xt[m], a);
#pragma unroll
                for (int j = 0; j < 4; ++j) a = fmaf(s_whh1[0][k * 4 + j], h[j], a);
                gate[k] = a;
            }
#pragma unroll
            for (int j = 0; j < 4; ++j) {
                float ig = sigf(gate[j]), fg = sigf(gate[4 + j]);
                float gg = tanhfast(gate[8 + j]), og = sigf(gate[12 + j]);
                c[j] = fmaf(fg, c[j], ig * gg);
                h[j] = og * tanhfast(c[j]);
            }
        }
#pragma unroll
        for (int j = 0; j < 4; ++j) g_last[sq * 8 + j] = h[j];
    } else {
        // backward: only step 0 of the reversed sequence is consumed
        // (it lands at original t = T-1). h0 = c0 = 0.
        int sl = tid - 16;
        int sq = blockIdx.x * 16 + sl;
        const float* hrow = s_h0 + sl * 516;
        float xt[8];
#pragma unroll
        for (int m = 0; m < 8; ++m) xt[m] = hrow[(TSTEPS - 1) * 8 + m];
        float gate[16];
#pragma unroll
        for (int k = 0; k < 16; ++k) {
            float a = s_b1[1][k];
#pragma unroll
            for (int m = 0; m < 8; ++m) a = fmaf(s_wih1[1][k * 8 + m], xt[m], a);
            gate[k] = a;
        }
#pragma unroll
        for (int j = 0; j < 4; ++j) {
            float ig = sigf(gate[j]);
            float gg = tanhfast(gate[8 + j]), og = sigf(gate[12 + j]);
            float cj = ig * gg;  // f*c0 = 0
            g_last[sq * 8 + 4 + j] = og * tanhfast(cj);
        }
    }
}

// ---------------------------------------------------------------------------
// Kernel 3: SE MLP. z[b] = g_last[b*512 .. b*512+511] (row-major reshape).
// h1 = relu(z @ w1.T) [2,32]; scale = sigmoid(h1 @ w2.T) [2,64].
// ---------------------------------------------------------------------------
__global__ void fc_kernel(const float* __restrict__ w1,
                          const float* __restrict__ w2) {
    __shared__ float z[1024];
    __shared__ float h1[2][32];
    int tid = threadIdx.x;  // 64 threads
    for (int k = tid; k < 1024; k += 64) z[k] = g_last[k];
    __syncthreads();
    {
        int b = tid >> 5, e = tid & 31;
        const float* wr = w1 + e * 512;
        const float* zb = z + b * 512;
        float acc = 0.f;
#pragma unroll 4
        for (int k = 0; k < 512; ++k) acc = fmaf(wr[k], zb[k], acc);
        h1[b][e] = fmaxf(acc, 0.f);
    }
    __syncthreads();
#pragma unroll
    for (int b = 0; b < 2; ++b) {
        float acc = 0.f;
#pragma unroll
        for (int m = 0; m < 32; ++m) acc = fmaf(w2[tid * 32 + m], h1[b][m], acc);
        g_scale[b * 64 + tid] = sigf(acc);
    }
}

// ---------------------------------------------------------------------------
// Kernel 4: out = x * scale[bc]. One float4 per thread, exact grid.
// ---------------------------------------------------------------------------
__global__ void scale_kernel(const float* __restrict__ x,
                             float* __restrict__ out) {
    unsigned v = blockIdx.x * 256u + threadIdx.x;  // < 18,874,368
    unsigned bc = v / VECS_PER_BC;                 // 0..127
    float sc = g_scale[bc];
    float4 t = reinterpret_cast<const float4*>(x)[v];
    t.x *= sc; t.y *= sc; t.z *= sc; t.w *= sc;
    reinterpret_cast<float4*>(out)[v] = t;
}

// ---------------------------------------------------------------------------
extern "C" void kernel_launch(void* const* d_in, const int* in_sizes, int n_in,
                              void* d_out, int out_size) {
    const float* x = (const float*)d_in[0];

    mean_kernel<<<8192, 256>>>(x);

    lstm_kernel<<<8, 32>>>(
        (const float*)d_in[1],  (const float*)d_in[2],
        (const float*)d_in[3],  (const float*)d_in[4],
        (const float*)d_in[5],  (const float*)d_in[6],
        (const float*)d_in[7],  (const float*)d_in[8],
        (const float*)d_in[9],  (const float*)d_in[10],
        (const float*)d_in[11], (const float*)d_in[12],
        (const float*)d_in[13], (const float*)d_in[14],
        (const float*)d_in[15], (const float*)d_in[16]);

    fc_kernel<<<1, 64>>>((const float*)d_in[17], (const float*)d_in[18]);

    // 75,497,472 elems / 4 per vec / 256 per block = 73728 blocks exactly
    scale_kernel<<<73728, 256>>>(x, (float*)d_out);
}

// round 2
// speedup vs baseline: 1.1092x; 1.1092x over previous
#include <cuda_runtime.h>

// Problem constants: x [2, 64, 64, 96, 96]; NSEQ = bs*c = 128; T = d = 64; HID = 4
#define NSEQ 128
#define TSTEPS 64
#define ROWVEC 2304          // 96*96/4
#define VECS_PER_BC 147456   // 64*96*96/4

__device__ float g_mean[NSEQ * TSTEPS];   // [seq=b*64+c][t=d]
__device__ float g_last[NSEQ * 8];        // last-timestep [fwd h(4) | bwd h(4)]
__device__ float g_scale[NSEQ];           // sigmoid output per (b,c)

__device__ __forceinline__ float sigf(float x) {
    return __fdividef(1.f, 1.f + __expf(-x));
}
__device__ __forceinline__ float tanhfast(float x) {
    return __fdividef(2.f, 1.f + __expf(-2.f * x)) - 1.f;
}

// ---------------------------------------------------------------------------
// Kernel 1: mean over H,W for each (b,c,d) row. One block per row.
// ---------------------------------------------------------------------------
__global__ void mean_kernel(const float* __restrict__ x) {
    int r = blockIdx.x;  // 0..8191
    const float4* p = reinterpret_cast<const float4*>(x) + (size_t)r * ROWVEC;
    float s = 0.f;
#pragma unroll
    for (int i = 0; i < 9; ++i) {
        float4 v = p[threadIdx.x + i * 256];
        s += (v.x + v.y) + (v.z + v.w);
    }
#pragma unroll
    for (int off = 16; off > 0; off >>= 1)
        s += __shfl_down_sync(0xffffffffu, s, off);
    __shared__ float red[8];
    int warp = threadIdx.x >> 5, lane = threadIdx.x & 31;
    if (lane == 0) red[warp] = s;
    __syncthreads();
    if (threadIdx.x < 8) {
        s = red[threadIdx.x];
        s += __shfl_down_sync(0xffu, s, 4);
        s += __shfl_down_sync(0xffu, s, 2);
        s += __shfl_down_sync(0xffu, s, 1);
        if (threadIdx.x == 0) g_mean[r] = s * (1.f / 9216.f);
    }
}

// ---------------------------------------------------------------------------
// Kernel 2: 2-layer biLSTM (hidden=4), 4 threads per LSTM cell.
// 32 blocks x 32 threads. Block covers 4 sequences (both directions).
// Layer 0: unit u = tid>>2 (0..7) -> (seq_local = u>>1, dir = u&1);
//          lane j = tid&3 owns cell j; h exchanged via width-4 shuffles.
// Layer 1: threads 0..15 = fwd (full 64 steps), threads 16..31 = bwd
//          (only its first step is consumed, since only t=T-1 survives).
// Weights are register-resident; layer-0 outputs staged in SMEM.
// ---------------------------------------------------------------------------
__global__ void lstm_kernel(
    const float* __restrict__ wih0f, const float* __restrict__ whh0f,
    const float* __restrict__ bih0f, const float* __restrict__ bhh0f,
    const float* __restrict__ wih0b, const float* __restrict__ whh0b,
    const float* __restrict__ bih0b, const float* __restrict__ bhh0b,
    const float* __restrict__ wih1f, const float* __restrict__ whh1f,
    const float* __restrict__ bih1f, const float* __restrict__ bhh1f,
    const float* __restrict__ wih1b, const float* __restrict__ whh1b,
    const float* __restrict__ bih1b, const float* __restrict__ bhh1b) {
    __shared__ float s_mean[256];      // 4 seqs x 64 t
    __shared__ float s_h0[4][516];     // 4 seqs x (64 t x 8 feat) + pad

    int tid = threadIdx.x;
    // stage this block's 4 sequences of means (contiguous 256 floats)
#pragma unroll
    for (int i = 0; i < 8; ++i)
        s_mean[tid + i * 32] = g_mean[blockIdx.x * 256 + tid + i * 32];

    int j   = tid & 3;        // cell index within hidden=4
    int u   = tid >> 2;       // unit 0..7
    int sl  = u >> 1;         // local seq 0..3
    int dir = u & 1;

    // ---- register-load layer-0 weights (rows j, 4+j, 8+j, 12+j) ----
    const float* WIH0 = dir ? wih0b : wih0f;
    const float* WHH0 = dir ? whh0b : whh0f;
    const float* BI0  = dir ? bih0b : bih0f;
    const float* BH0  = dir ? bhh0b : bhh0f;
    float w_ih0[4], w_hh0[16], b0[4];
#pragma unroll
    for (int g = 0; g < 4; ++g) {
        int k = g * 4 + j;
        w_ih0[g] = WIH0[k];
        b0[g]    = BI0[k] + BH0[k];
#pragma unroll
        for (int m = 0; m < 4; ++m) w_hh0[g * 4 + m] = WHH0[k * 4 + m];
    }
    // ---- register-load layer-1 weights (fwd for tid<16, bwd otherwise) ----
    const float* WIH1 = (tid < 16) ? wih1f : wih1b;
    const float* WHH1 = (tid < 16) ? whh1f : whh1b;
    const float* BI1  = (tid < 16) ? bih1f : bih1b;
    const float* BH1  = (tid < 16) ? bhh1f : bhh1b;
    int j1 = tid & 3;
    float w1i[32], w1h[16], b1[4];
#pragma unroll
    for (int g = 0; g < 4; ++g) {
        int k = g * 4 + j1;
        b1[g] = BI1[k] + BH1[k];
#pragma unroll
        for (int m = 0; m < 8; ++m) w1i[g * 8 + m] = WIH1[k * 8 + m];
#pragma unroll
        for (int m = 0; m < 4; ++m) w1h[g * 4 + m] = WHH1[k * 4 + m];
    }
    __syncthreads();

    // ---------------- layer 0 ----------------
    {
        float hj = 0.f, cj = 0.f;
        const float* mrow = s_mean + sl * 64;
        float* hrow = s_h0[sl];
        int foff = dir * 4 + j;
        for (int st = 0; st < TSTEPS; ++st) {
            int t = dir ? (TSTEPS - 1 - st) : st;
            float xt = mrow[t];
            float h0 = __shfl_sync(0xffffffffu, hj, 0, 4);
            float h1 = __shfl_sync(0xffffffffu, hj, 1, 4);
            float h2 = __shfl_sync(0xffffffffu, hj, 2, 4);
            float h3 = __shfl_sync(0xffffffffu, hj, 3, 4);
            float ga[4];
#pragma unroll
            for (int g = 0; g < 4; ++g) {
                float a = fmaf(w_ih0[g], xt, b0[g]);
                a = fmaf(w_hh0[g * 4 + 0], h0, a);
                a = fmaf(w_hh0[g * 4 + 1], h1, a);
                a = fmaf(w_hh0[g * 4 + 2], h2, a);
                a = fmaf(w_hh0[g * 4 + 3], h3, a);
                ga[g] = a;
            }
            float ig = sigf(ga[0]), fg = sigf(ga[1]);
            float gg = tanhfast(ga[2]), og = sigf(ga[3]);
            cj = fmaf(fg, cj, ig * gg);
            hj = og * tanhfast(cj);
            hrow[t * 8 + foff] = hj;
        }
    }
    __syncthreads();

    // ---------------- layer 1 ----------------
    if (tid < 16) {
        // forward: full 64 steps, keep final h
        int s1 = tid >> 2;
        const float* hrow = s_h0[s1];
        float hj = 0.f, cj = 0.f;
        for (int t = 0; t < TSTEPS; ++t) {
            float4 xa = *reinterpret_cast<const float4*>(hrow + t * 8);
            float4 xb = *reinterpret_cast<const float4*>(hrow + t * 8 + 4);
            float h0 = __shfl_sync(0x0000ffffu, hj, 0, 4);
            float h1 = __shfl_sync(0x0000ffffu, hj, 1, 4);
            float h2 = __shfl_sync(0x0000ffffu, hj, 2, 4);
            float h3 = __shfl_sync(0x0000ffffu, hj, 3, 4);
            float ga[4];
#pragma unroll
            for (int g = 0; g < 4; ++g) {
                float a = b1[g];
                a = fmaf(w1i[g * 8 + 0], xa.x, a);
                a = fmaf(w1i[g * 8 + 1], xa.y, a);
                a = fmaf(w1i[g * 8 + 2], xa.z, a);
                a = fmaf(w1i[g * 8 + 3], xa.w, a);
                a = fmaf(w1i[g * 8 + 4], xb.x, a);
                a = fmaf(w1i[g * 8 + 5], xb.y, a);
                a = fmaf(w1i[g * 8 + 6], xb.z, a);
                a = fmaf(w1i[g * 8 + 7], xb.w, a);
                a = fmaf(w1h[g * 4 + 0], h0, a);
                a = fmaf(w1h[g * 4 + 1], h1, a);
                a = fmaf(w1h[g * 4 + 2], h2, a);
                a = fmaf(w1h[g * 4 + 3], h3, a);
                ga[g] = a;
            }
            float ig = sigf(ga[0]), fg = sigf(ga[1]);
            float gg = tanhfast(ga[2]), og = sigf(ga[3]);
            cj = fmaf(fg, cj, ig * gg);
            hj = og * tanhfast(cj);
        }
        g_last[(blockIdx.x * 4 + s1) * 8 + j1] = hj;
    } else {
        // backward: only the first processed step (original t = T-1) is used.
        // h0 = c0 = 0 -> forget-gate term vanishes.
        int s1 = (tid - 16) >> 2;
        const float* hrow = s_h0[s1];
        float4 xa = *reinterpret_cast<const float4*>(hrow + (TSTEPS - 1) * 8);
        float4 xb = *reinterpret_cast<const float4*>(hrow + (TSTEPS - 1) * 8 + 4);
        float ga[4];
#pragma unroll
        for (int g = 0; g < 4; ++g) {
            float a = b1[g];
            a = fmaf(w1i[g * 8 + 0], xa.x, a);
            a = fmaf(w1i[g * 8 + 1], xa.y, a);
            a = fmaf(w1i[g * 8 + 2], xa.z, a);
            a = fmaf(w1i[g * 8 + 3], xa.w, a);
            a = fmaf(w1i[g * 8 + 4], xb.x, a);
            a = fmaf(w1i[g * 8 + 5], xb.y, a);
            a = fmaf(w1i[g * 8 + 6], xb.z, a);
            a = fmaf(w1i[g * 8 + 7], xb.w, a);
            ga[g] = a;
        }
        float cj = sigf(ga[0]) * tanhfast(ga[2]);
        float hj = sigf(ga[3]) * tanhfast(cj);
        g_last[(blockIdx.x * 4 + s1) * 8 + 4 + j1] = hj;
    }
}

// ---------------------------------------------------------------------------
// Kernel 3: SE MLP. z[b] = g_last[b*512 .. +511]; h1 = relu(z @ w1.T) [2,32];
// scale = sigmoid(h1 @ w2.T) [2,64].
// ---------------------------------------------------------------------------
__global__ void fc_kernel(const float* __restrict__ w1,
                          const float* __restrict__ w2) {
    __shared__ float z[1024];
    __shared__ float h1[2][32];
    int tid = threadIdx.x;  // 64 threads
    for (int k = tid; k < 1024; k += 64) z[k] = g_last[k];
    __syncthreads();
    {
        int b = tid >> 5, e = tid & 31;
        const float* wr = w1 + e * 512;
        const float* zb = z + b * 512;
        float acc = 0.f;
#pragma unroll 4
        for (int k = 0; k < 512; ++k) acc = fmaf(wr[k], zb[k], acc);
        h1[b][e] = fmaxf(acc, 0.f);
    }
    __syncthreads();
#pragma unroll
    for (int b = 0; b < 2; ++b) {
        float acc = 0.f;
#pragma unroll
        for (int m = 0; m < 32; ++m) acc = fmaf(w2[tid * 32 + m], h1[b][m], acc);
        g_scale[b * 64 + tid] = sigf(acc);
    }
}

// ---------------------------------------------------------------------------
// Kernel 4: out = x * scale[bc]. One float4 per thread, exact grid.
// ---------------------------------------------------------------------------
__global__ void scale_kernel(const float* __restrict__ x,
                             float* __restrict__ out) {
    unsigned v = blockIdx.x * 256u + threadIdx.x;  // < 18,874,368
    unsigned bc = v / VECS_PER_BC;                 // 0..127
    float sc = g_scale[bc];
    float4 t = reinterpret_cast<const float4*>(x)[v];
    t.x *= sc; t.y *= sc; t.z *= sc; t.w *= sc;
    reinterpret_cast<float4*>(out)[v] = t;
}

// ---------------------------------------------------------------------------
extern "C" void kernel_launch(void* const* d_in, const int* in_sizes, int n_in,
                              void* d_out, int out_size) {
    const float* x = (const float*)d_in[0];

    mean_kernel<<<8192, 256>>>(x);

    lstm_kernel<<<32, 32>>>(
        (const float*)d_in[1],  (const float*)d_in[2],
        (const float*)d_in[3],  (const float*)d_in[4],
        (const float*)d_in[5],  (const float*)d_in[6],
        (const float*)d_in[7],  (const float*)d_in[8],
        (const float*)d_in[9],  (const float*)d_in[10],
        (const float*)d_in[11], (const float*)d_in[12],
        (const float*)d_in[13], (const float*)d_in[14],
        (const float*)d_in[15], (const float*)d_in[16]);

    fc_kernel<<<1, 64>>>((const float*)d_in[17], (const float*)d_in[18]);

    scale_kernel<<<73728, 256>>>(x, (float*)d_out);
}

// round 3
// speedup vs baseline: 1.1334x; 1.0219x over previous
#include <cuda_runtime.h>

// Problem constants: x [2, 64, 64, 96, 96]; NSEQ = bs*c = 128; T = d = 64; HID = 4
#define NSEQ 128
#define TSTEPS 64
#define ROWVEC 2304          // 96*96/4
#define VECS_PER_BC 147456   // 64*96*96/4

__device__ float g_mean[NSEQ * TSTEPS];   // [seq=b*64+c][t=d]
__device__ float g_last[NSEQ * 8];        // last-timestep [fwd h(4) | bwd h(4)]
__device__ float g_scale[NSEQ];           // sigmoid output per (b,c)

__device__ __forceinline__ float sigf(float x) {
    return __fdividef(1.f, 1.f + __expf(-x));
}
__device__ __forceinline__ float tanhfast(float x) {
    return __fdividef(2.f, 1.f + __expf(-2.f * x)) - 1.f;
}

// ---------------------------------------------------------------------------
// Kernel 1: mean over H,W for each (b,c,d) row. One block per row.
// ROW ORDER REVERSED: the last-executing blocks read the LOWEST addresses of
// x, so L2 (126MB) ends up holding x[0..~126MB] — which scale_kernel then
// reads first, converting ~100MB of its DRAM reads into L2 hits.
// ---------------------------------------------------------------------------
__global__ void mean_kernel(const float* __restrict__ x) {
    int r = 8191 - blockIdx.x;
    const float4* p = reinterpret_cast<const float4*>(x) + (size_t)r * ROWVEC;
    float s0 = 0.f, s1 = 0.f;
#pragma unroll
    for (int i = 0; i < 9; i += 2) {
        float4 v = p[threadIdx.x + i * 256];
        s0 += (v.x + v.y) + (v.z + v.w);
        if (i + 1 < 9) {
            float4 w = p[threadIdx.x + (i + 1) * 256];
            s1 += (w.x + w.y) + (w.z + w.w);
        }
    }
    float s = s0 + s1;
#pragma unroll
    for (int off = 16; off > 0; off >>= 1)
        s += __shfl_down_sync(0xffffffffu, s, off);
    __shared__ float red[8];
    int warp = threadIdx.x >> 5, lane = threadIdx.x & 31;
    if (lane == 0) red[warp] = s;
    __syncthreads();
    if (threadIdx.x < 8) {
        s = red[threadIdx.x];
        s += __shfl_down_sync(0xffu, s, 4);
        s += __shfl_down_sync(0xffu, s, 2);
        s += __shfl_down_sync(0xffu, s, 1);
        if (threadIdx.x == 0) g_mean[r] = s * (1.f / 9216.f);
    }
}

// ---------------------------------------------------------------------------
// Kernel 2: 2-layer biLSTM (hidden=4), 4 threads per LSTM cell.
// 32 blocks x 32 threads; block covers 4 sequences (both directions).
// Gate sums computed as balanced FMA trees to shorten the serial dep chain.
// ---------------------------------------------------------------------------
__global__ void lstm_kernel(
    const float* __restrict__ wih0f, const float* __restrict__ whh0f,
    const float* __restrict__ bih0f, const float* __restrict__ bhh0f,
    const float* __restrict__ wih0b, const float* __restrict__ whh0b,
    const float* __restrict__ bih0b, const float* __restrict__ bhh0b,
    const float* __restrict__ wih1f, const float* __restrict__ whh1f,
    const float* __restrict__ bih1f, const float* __restrict__ bhh1f,
    const float* __restrict__ wih1b, const float* __restrict__ whh1b,
    const float* __restrict__ bih1b, const float* __restrict__ bhh1b) {
    __shared__ float s_mean[256];      // 4 seqs x 64 t
    __shared__ float s_h0[4][516];     // 4 seqs x (64 t x 8 feat) + pad

    int tid = threadIdx.x;
#pragma unroll
    for (int i = 0; i < 8; ++i)
        s_mean[tid + i * 32] = g_mean[blockIdx.x * 256 + tid + i * 32];

    int j   = tid & 3;        // cell index within hidden=4
    int u   = tid >> 2;       // unit 0..7
    int sl  = u >> 1;         // local seq 0..3
    int dir = u & 1;

    // ---- register-load layer-0 weights (rows j, 4+j, 8+j, 12+j) ----
    const float* WIH0 = dir ? wih0b : wih0f;
    const float* WHH0 = dir ? whh0b : whh0f;
    const float* BI0  = dir ? bih0b : bih0f;
    const float* BH0  = dir ? bhh0b : bhh0f;
    float w_ih0[4], w_hh0[16], b0[4];
#pragma unroll
    for (int g = 0; g < 4; ++g) {
        int k = g * 4 + j;
        w_ih0[g] = WIH0[k];
        b0[g]    = BI0[k] + BH0[k];
#pragma unroll
        for (int m = 0; m < 4; ++m) w_hh0[g * 4 + m] = WHH0[k * 4 + m];
    }
    // ---- register-load layer-1 weights (fwd for tid<16, bwd otherwise) ----
    const float* WIH1 = (tid < 16) ? wih1f : wih1b;
    const float* WHH1 = (tid < 16) ? whh1f : whh1b;
    const float* BI1  = (tid < 16) ? bih1f : bih1b;
    const float* BH1  = (tid < 16) ? bhh1f : bhh1b;
    int j1 = tid & 3;
    float w1i[32], w1h[16], b1[4];
#pragma unroll
    for (int g = 0; g < 4; ++g) {
        int k = g * 4 + j1;
        b1[g] = BI1[k] + BH1[k];
#pragma unroll
        for (int m = 0; m < 8; ++m) w1i[g * 8 + m] = WIH1[k * 8 + m];
#pragma unroll
        for (int m = 0; m < 4; ++m) w1h[g * 4 + m] = WHH1[k * 4 + m];
    }
    __syncthreads();

    // ---------------- layer 0 ----------------
    {
        float hj = 0.f, cj = 0.f;
        const float* mrow = s_mean + sl * 64;
        float* hrow = s_h0[sl];
        int foff = dir * 4 + j;
        for (int st = 0; st < TSTEPS; ++st) {
            int t = dir ? (TSTEPS - 1 - st) : st;
            float xt = mrow[t];
            float h0 = __shfl_sync(0xffffffffu, hj, 0, 4);
            float h1 = __shfl_sync(0xffffffffu, hj, 1, 4);
            float h2 = __shfl_sync(0xffffffffu, hj, 2, 4);
            float h3 = __shfl_sync(0xffffffffu, hj, 3, 4);
            float ga[4];
#pragma unroll
            for (int g = 0; g < 4; ++g) {
                // balanced: (b + w*x + wh0*h0) + (wh1*h1 + wh2*h2) + wh3*h3
                float p0 = fmaf(w_ih0[g], xt, b0[g]);
                p0 = fmaf(w_hh0[g * 4 + 0], h0, p0);
                float p1 = fmaf(w_hh0[g * 4 + 2], h2, w_hh0[g * 4 + 1] * h1);
                float p2 = w_hh0[g * 4 + 3] * h3;
                ga[g] = p0 + (p1 + p2);
            }
            float ig = sigf(ga[0]), fg = sigf(ga[1]);
            float gg = tanhfast(ga[2]), og = sigf(ga[3]);
            cj = fmaf(fg, cj, ig * gg);
            hj = og * tanhfast(cj);
            hrow[t * 8 + foff] = hj;
        }
    }
    __syncthreads();

    // ---------------- layer 1 ----------------
    if (tid < 16) {
        // forward: full 64 steps, keep final h
        int s1 = tid >> 2;
        const float* hrow = s_h0[s1];
        float hj = 0.f, cj = 0.f;
        for (int t = 0; t < TSTEPS; ++t) {
            float4 xa = *reinterpret_cast<const float4*>(hrow + t * 8);
            float4 xb = *reinterpret_cast<const float4*>(hrow + t * 8 + 4);
            float h0 = __shfl_sync(0x0000ffffu, hj, 0, 4);
            float h1 = __shfl_sync(0x0000ffffu, hj, 1, 4);
            float h2 = __shfl_sync(0x0000ffffu, hj, 2, 4);
            float h3 = __shfl_sync(0x0000ffffu, hj, 3, 4);
            float ga[4];
#pragma unroll
            for (int g = 0; g < 4; ++g) {
                const float* wi = w1i + g * 8;
                const float* wh = w1h + g * 4;
                // balanced tree over 13 terms
                float p0 = fmaf(wi[0], xa.x, b1[g]);
                p0 = fmaf(wi[1], xa.y, p0);
                float p1 = fmaf(wi[3], xa.w, wi[2] * xa.z);
                float p2 = fmaf(wi[5], xb.y, wi[4] * xb.x);
                float p3 = fmaf(wi[7], xb.w, wi[6] * xb.z);
                float p4 = fmaf(wh[1], h1, wh[0] * h0);
                float p5 = fmaf(wh[3], h3, wh[2] * h2);
                ga[g] = ((p0 + p1) + (p2 + p3)) + (p4 + p5);
            }
            float ig = sigf(ga[0]), fg = sigf(ga[1]);
            float gg = tanhfast(ga[2]), og = sigf(ga[3]);
            cj = fmaf(fg, cj, ig * gg);
            hj = og * tanhfast(cj);
        }
        g_last[(blockIdx.x * 4 + s1) * 8 + j1] = hj;
    } else {
        // backward: only the first processed step (original t = T-1) is used.
        int s1 = (tid - 16) >> 2;
        const float* hrow = s_h0[s1];
        float4 xa = *reinterpret_cast<const float4*>(hrow + (TSTEPS - 1) * 8);
        float4 xb = *reinterpret_cast<const float4*>(hrow + (TSTEPS - 1) * 8 + 4);
        float ga[4];
#pragma unroll
        for (int g = 0; g < 4; ++g) {
            const float* wi = w1i + g * 8;
            float p0 = fmaf(wi[0], xa.x, b1[g]);
            p0 = fmaf(wi[1], xa.y, p0);
            float p1 = fmaf(wi[3], xa.w, wi[2] * xa.z);
            float p2 = fmaf(wi[5], xb.y, wi[4] * xb.x);
            float p3 = fmaf(wi[7], xb.w, wi[6] * xb.z);
            ga[g] = (p0 + p1) + (p2 + p3);
        }
        float cj = sigf(ga[0]) * tanhfast(ga[2]);
        float hj = sigf(ga[3]) * tanhfast(cj);
        g_last[(blockIdx.x * 4 + s1) * 8 + 4 + j1] = hj;
    }
}

// ---------------------------------------------------------------------------
// Kernel 3: SE MLP. z[b] = g_last[b*512 .. +511]; h1 = relu(z @ w1.T) [2,32];
// scale = sigmoid(h1 @ w2.T) [2,64].
// ---------------------------------------------------------------------------
__global__ void fc_kernel(const float* __restrict__ w1,
                          const float* __restrict__ w2) {
    __shared__ float z[1024];
    __shared__ float h1[2][32];
    int tid = threadIdx.x;  // 64 threads
    for (int k = tid; k < 1024; k += 64) z[k] = g_last[k];
    __syncthreads();
    {
        int b = tid >> 5, e = tid & 31;
        const float* wr = w1 + e * 512;
        const float* zb = z + b * 512;
        float acc = 0.f;
#pragma unroll 4
        for (int k = 0; k < 512; ++k) acc = fmaf(wr[k], zb[k], acc);
        h1[b][e] = fmaxf(acc, 0.f);
    }
    __syncthreads();
#pragma unroll
    for (int b = 0; b < 2; ++b) {
        float acc = 0.f;
#pragma unroll
        for (int m = 0; m < 32; ++m) acc = fmaf(w2[tid * 32 + m], h1[b][m], acc);
        g_scale[b * 64 + tid] = sigf(acc);
    }
}

// ---------------------------------------------------------------------------
// Kernel 4: out = x * scale[bc]. One float4 per thread, exact grid.
// Reads ascend from x[0] — hitting the L2 prefix left by mean_kernel.
// Stores are streaming (.cs) so they do not evict that prefix.
// ---------------------------------------------------------------------------
__global__ void scale_kernel(const float* __restrict__ x,
                             float* __restrict__ out) {
    unsigned v = blockIdx.x * 256u + threadIdx.x;  // < 18,874,368
    unsigned bc = v / VECS_PER_BC;                 // 0..127
    float sc = g_scale[bc];
    float4 t = reinterpret_cast<const float4*>(x)[v];
    t.x *= sc; t.y *= sc; t.z *= sc; t.w *= sc;
    __stcs(reinterpret_cast<float4*>(out) + v, t);
}

// ---------------------------------------------------------------------------
extern "C" void kernel_launch(void* const* d_in, const int* in_sizes, int n_in,
                              void* d_out, int out_size) {
    const float* x = (const float*)d_in[0];

    mean_kernel<<<8192, 256>>>(x);

    lstm_kernel<<<32, 32>>>(
        (const float*)d_in[1],  (const float*)d_in[2],
        (const float*)d_in[3],  (const float*)d_in[4],
        (const float*)d_in[5],  (const float*)d_in[6],
        (const float*)d_in[7],  (const float*)d_in[8],
        (const float*)d_in[9],  (const float*)d_in[10],
        (const float*)d_in[11], (const float*)d_in[12],
        (const float*)d_in[13], (const float*)d_in[14],
        (const float*)d_in[15], (const float*)d_in[16]);

    fc_kernel<<<1, 64>>>((const float*)d_in[17], (const float*)d_in[18]);

    scale_kernel<<<73728, 256>>>(x, (float*)d_out);
}

// round 4
// speedup vs baseline: 1.2839x; 1.1328x over previous
#include <cuda_runtime.h>

// Problem constants: x [2, 64, 64, 96, 96]; NSEQ = bs*c = 128; T = d = 64; HID = 4
#define NSEQ 128
#define TSTEPS 64
#define ROWVEC 2304          // 96*96/4
#define VECS_PER_BC 147456   // 64*96*96/4

__device__ float g_mean[NSEQ * TSTEPS];   // [seq=b*64+c][t=d]
__device__ float g_last[NSEQ * 8];        // last-timestep [fwd h(4) | bwd h(4)]
__device__ float g_scale[NSEQ];           // sigmoid output per (b,c)
__device__ unsigned g_ctr;                // last-block counter (self-resetting)

__device__ __forceinline__ float tanh_ap(float x) {
    float y;
    asm("tanh.approx.f32 %0, %1;" : "=f"(y) : "f"(x));
    return y;
}
__device__ __forceinline__ float sig_ap(float x) {
    return fmaf(0.5f, tanh_ap(0.5f * x), 0.5f);
}
__device__ __forceinline__ float sig_acc(float x) {
    return __fdividef(1.f, 1.f + __expf(-x));
}

// ---------------------------------------------------------------------------
// Kernel 1: mean over H,W for each (b,c,d) row. One block per row.
// Loads front-batched into a register array for max MLP.
// ---------------------------------------------------------------------------
__global__ void mean_kernel(const float* __restrict__ x) {
    int r = 8191 - blockIdx.x;
    const float4* p = reinterpret_cast<const float4*>(x) + (size_t)r * ROWVEC;
    float4 v[9];
#pragma unroll
    for (int i = 0; i < 9; ++i) v[i] = p[threadIdx.x + i * 256];
    float s = 0.f;
#pragma unroll
    for (int i = 0; i < 9; ++i) s += (v[i].x + v[i].y) + (v[i].z + v[i].w);
#pragma unroll
    for (int off = 16; off > 0; off >>= 1)
        s += __shfl_down_sync(0xffffffffu, s, off);
    __shared__ float red[8];
    int warp = threadIdx.x >> 5, lane = threadIdx.x & 31;
    if (lane == 0) red[warp] = s;
    __syncthreads();
    if (threadIdx.x < 8) {
        s = red[threadIdx.x];
        s += __shfl_down_sync(0xffu, s, 4);
        s += __shfl_down_sync(0xffu, s, 2);
        s += __shfl_down_sync(0xffu, s, 1);
        if (threadIdx.x == 0) g_mean[r] = s * (1.f / 9216.f);
    }
}

// ---------------------------------------------------------------------------
// Kernel 2: 2-layer biLSTM (hidden=4), 4 threads per cell, tanh.approx
// activations. 32 blocks x 32 threads; block covers 4 sequences.
// The LAST block to finish additionally runs the SE MLP (fc) and writes
// g_scale, then resets the counter for graph replay determinism.
// ---------------------------------------------------------------------------
__global__ void lstm_kernel(
    const float* __restrict__ wih0f, const float* __restrict__ whh0f,
    const float* __restrict__ bih0f, const float* __restrict__ bhh0f,
    const float* __restrict__ wih0b, const float* __restrict__ whh0b,
    const float* __restrict__ bih0b, const float* __restrict__ bhh0b,
    const float* __restrict__ wih1f, const float* __restrict__ whh1f,
    const float* __restrict__ bih1f, const float* __restrict__ bhh1f,
    const float* __restrict__ wih1b, const float* __restrict__ whh1b,
    const float* __restrict__ bih1b, const float* __restrict__ bhh1b,
    const float* __restrict__ w1,    const float* __restrict__ w2) {
    __shared__ float s_mean[256];      // 4 seqs x 64 t
    __shared__ float s_h0[4][516];     // 4 seqs x (64 t x 8 feat) + pad

    int tid = threadIdx.x;
#pragma unroll
    for (int i = 0; i < 8; ++i)
        s_mean[tid + i * 32] = g_mean[blockIdx.x * 256 + tid + i * 32];

    int j   = tid & 3;        // cell index within hidden=4
    int u   = tid >> 2;       // unit 0..7
    int sl  = u >> 1;         // local seq 0..3
    int dir = u & 1;

    // ---- register-load layer-0 weights (rows j, 4+j, 8+j, 12+j) ----
    const float* WIH0 = dir ? wih0b : wih0f;
    const float* WHH0 = dir ? whh0b : whh0f;
    const float* BI0  = dir ? bih0b : bih0f;
    const float* BH0  = dir ? bhh0b : bhh0f;
    float w_ih0[4], w_hh0[16], b0[4];
#pragma unroll
    for (int g = 0; g < 4; ++g) {
        int k = g * 4 + j;
        w_ih0[g] = WIH0[k];
        b0[g]    = BI0[k] + BH0[k];
#pragma unroll
        for (int m = 0; m < 4; ++m) w_hh0[g * 4 + m] = WHH0[k * 4 + m];
    }
    // ---- register-load layer-1 weights (fwd for tid<16, bwd otherwise) ----
    const float* WIH1 = (tid < 16) ? wih1f : wih1b;
    const float* WHH1 = (tid < 16) ? whh1f : whh1b;
    const float* BI1  = (tid < 16) ? bih1f : bih1b;
    const float* BH1  = (tid < 16) ? bhh1f : bhh1b;
    int j1 = tid & 3;
    float w1i[32], w1h[16], b1[4];
#pragma unroll
    for (int g = 0; g < 4; ++g) {
        int k = g * 4 + j1;
        b1[g] = BI1[k] + BH1[k];
#pragma unroll
        for (int m = 0; m < 8; ++m) w1i[g * 8 + m] = WIH1[k * 8 + m];
#pragma unroll
        for (int m = 0; m < 4; ++m) w1h[g * 4 + m] = WHH1[k * 4 + m];
    }
    __syncthreads();

    // ---------------- layer 0 ----------------
    {
        float hj = 0.f, cj = 0.f;
        const float* mrow = s_mean + sl * 64;
        float* hrow = s_h0[sl];
        int foff = dir * 4 + j;
        for (int st = 0; st < TSTEPS; ++st) {
            int t = dir ? (TSTEPS - 1 - st) : st;
            float xt = mrow[t];
            float h0 = __shfl_sync(0xffffffffu, hj, 0, 4);
            float h1 = __shfl_sync(0xffffffffu, hj, 1, 4);
            float h2 = __shfl_sync(0xffffffffu, hj, 2, 4);
            float h3 = __shfl_sync(0xffffffffu, hj, 3, 4);
            float ga[4];
#pragma unroll
            for (int g = 0; g < 4; ++g) {
                float p0 = fmaf(w_ih0[g], xt, b0[g]);
                p0 = fmaf(w_hh0[g * 4 + 0], h0, p0);
                float p1 = fmaf(w_hh0[g * 4 + 2], h2, w_hh0[g * 4 + 1] * h1);
                float p2 = w_hh0[g * 4 + 3] * h3;
                ga[g] = p0 + (p1 + p2);
            }
            float ig = sig_ap(ga[0]), fg = sig_ap(ga[1]);
            float gg = tanh_ap(ga[2]), og = sig_ap(ga[3]);
            cj = fmaf(fg, cj, ig * gg);
            hj = og * tanh_ap(cj);
            hrow[t * 8 + foff] = hj;
        }
    }
    __syncthreads();

    // ---------------- layer 1 ----------------
    if (tid < 16) {
        // forward: full 64 steps, keep final h
        int s1 = tid >> 2;
        const float* hrow = s_h0[s1];
        float hj = 0.f, cj = 0.f;
        for (int t = 0; t < TSTEPS; ++t) {
            float4 xa = *reinterpret_cast<const float4*>(hrow + t * 8);
            float4 xb = *reinterpret_cast<const float4*>(hrow + t * 8 + 4);
            float h0 = __shfl_sync(0x0000ffffu, hj, 0, 4);
            float h1 = __shfl_sync(0x0000ffffu, hj, 1, 4);
            float h2 = __shfl_sync(0x0000ffffu, hj, 2, 4);
            float h3 = __shfl_sync(0x0000ffffu, hj, 3, 4);
            float ga[4];
#pragma unroll
            for (int g = 0; g < 4; ++g) {
                const float* wi = w1i + g * 8;
                const float* wh = w1h + g * 4;
                float p0 = fmaf(wi[0], xa.x, b1[g]);
                p0 = fmaf(wi[1], xa.y, p0);
                float p1 = fmaf(wi[3], xa.w, wi[2] * xa.z);
                float p2 = fmaf(wi[5], xb.y, wi[4] * xb.x);
                float p3 = fmaf(wi[7], xb.w, wi[6] * xb.z);
                float p4 = fmaf(wh[1], h1, wh[0] * h0);
                float p5 = fmaf(wh[3], h3, wh[2] * h2);
                ga[g] = ((p0 + p1) + (p2 + p3)) + (p4 + p5);
            }
            float ig = sig_ap(ga[0]), fg = sig_ap(ga[1]);
            float gg = tanh_ap(ga[2]), og = sig_ap(ga[3]);
            cj = fmaf(fg, cj, ig * gg);
            hj = og * tanh_ap(cj);
        }
        g_last[(blockIdx.x * 4 + s1) * 8 + j1] = hj;
    } else {
        // backward: only the first processed step (original t = T-1) is used.
        int s1 = (tid - 16) >> 2;
        const float* hrow = s_h0[s1];
        float4 xa = *reinterpret_cast<const float4*>(hrow + (TSTEPS - 1) * 8);
        float4 xb = *reinterpret_cast<const float4*>(hrow + (TSTEPS - 1) * 8 + 4);
        float ga[4];
#pragma unroll
        for (int g = 0; g < 4; ++g) {
            const float* wi = w1i + g * 8;
            float p0 = fmaf(wi[0], xa.x, b1[g]);
            p0 = fmaf(wi[1], xa.y, p0);
            float p1 = fmaf(wi[3], xa.w, wi[2] * xa.z);
            float p2 = fmaf(wi[5], xb.y, wi[4] * xb.x);
            float p3 = fmaf(wi[7], xb.w, wi[6] * xb.z);
            ga[g] = (p0 + p1) + (p2 + p3);
        }
        float cj = sig_ap(ga[0]) * tanh_ap(ga[2]);
        float hj = sig_ap(ga[3]) * tanh_ap(cj);
        g_last[(blockIdx.x * 4 + s1) * 8 + 4 + j1] = hj;
    }

    // ---------------- fc (SE MLP) in the last-arriving block ----------------
    __syncthreads();
    __shared__ unsigned s_last;
    if (tid == 0) {
        __threadfence();
        s_last = (atomicAdd(&g_ctr, 1u) == 31u);
    }
    __syncthreads();
    if (!s_last) return;
    __threadfence();  // acquire: make other blocks' g_last stores visible

    __shared__ float z[1024];
    __shared__ float h1s[64];
    for (int k = tid; k < 1024; k += 32) z[k] = g_last[k];
    __syncwarp();
    {
        const float* wr = w1 + tid * 512;
        float a0 = 0, a1 = 0, a2 = 0, a3 = 0;   // b = 0
        float c0 = 0, c1 = 0, c2 = 0, c3 = 0;   // b = 1
#pragma unroll 4
        for (int k = 0; k < 512; k += 4) {
            float wk0 = wr[k], wk1 = wr[k + 1], wk2 = wr[k + 2], wk3 = wr[k + 3];
            a0 = fmaf(wk0, z[k], a0);       a1 = fmaf(wk1, z[k + 1], a1);
            a2 = fmaf(wk2, z[k + 2], a2);   a3 = fmaf(wk3, z[k + 3], a3);
            c0 = fmaf(wk0, z[512 + k], c0); c1 = fmaf(wk1, z[513 + k], c1);
            c2 = fmaf(wk2, z[514 + k], c2); c3 = fmaf(wk3, z[515 + k], c3);
        }
        h1s[tid]      = fmaxf((a0 + a1) + (a2 + a3), 0.f);
        h1s[32 + tid] = fmaxf((c0 + c1) + (c2 + c3), 0.f);
    }
    __syncwarp();
#pragma unroll
    for (int i = 0; i < 4; ++i) {
        int idx = tid + i * 32;          // 0..127 -> (b = idx>>6, ch = idx&63)
        int b = idx >> 6, ch = idx & 63;
        const float* wr = w2 + ch * 32;
        const float* hb = h1s + b * 32;
        float acc = 0.f;
#pragma unroll
        for (int m = 0; m < 32; ++m) acc = fmaf(wr[m], hb[m], acc);
        g_scale[idx] = sig_acc(acc);
    }
    if (tid == 0) g_ctr = 0;  // reset for next graph replay
}

// ---------------------------------------------------------------------------
// Kernel 3: out = x * scale[bc]. Block = 1024 consecutive float4s (all in one
// bc since 147456 % 1024 == 0). 4 float4 per thread, streaming hints.
// ---------------------------------------------------------------------------
__global__ void scale_kernel(const float* __restrict__ x,
                             float* __restrict__ out) {
    unsigned base = blockIdx.x * 1024u + threadIdx.x;
    float sc = g_scale[blockIdx.x / 144u];   // 147456/1024 = 144 blocks per bc
    const float4* px = reinterpret_cast<const float4*>(x);
    float4* po = reinterpret_cast<float4*>(out);
    float4 v0 = __ldcs(px + base);
    float4 v1 = __ldcs(px + base + 256);
    float4 v2 = __ldcs(px + base + 512);
    float4 v3 = __ldcs(px + base + 768);
    v0.x *= sc; v0.y *= sc; v0.z *= sc; v0.w *= sc;
    v1.x *= sc; v1.y *= sc; v1.z *= sc; v1.w *= sc;
    v2.x *= sc; v2.y *= sc; v2.z *= sc; v2.w *= sc;
    v3.x *= sc; v3.y *= sc; v3.z *= sc; v3.w *= sc;
    __stcs(po + base, v0);
    __stcs(po + base + 256, v1);
    __stcs(po + base + 512, v2);
    __stcs(po + base + 768, v3);
}

// ---------------------------------------------------------------------------
extern "C" void kernel_launch(void* const* d_in, const int* in_sizes, int n_in,
                              void* d_out, int out_size) {
    const float* x = (const float*)d_in[0];

    mean_kernel<<<8192, 256>>>(x);

    lstm_kernel<<<32, 32>>>(
        (const float*)d_in[1],  (const float*)d_in[2],
        (const float*)d_in[3],  (const float*)d_in[4],
        (const float*)d_in[5],  (const float*)d_in[6],
        (const float*)d_in[7],  (const float*)d_in[8],
        (const float*)d_in[9],  (const float*)d_in[10],
        (const float*)d_in[11], (const float*)d_in[12],
        (const float*)d_in[13], (const float*)d_in[14],
        (const float*)d_in[15], (const float*)d_in[16],
        (const float*)d_in[17], (const float*)d_in[18]);

    scale_kernel<<<18432, 256>>>(x, (float*)d_out);
}